// round 9
// baseline (speedup 1.0000x reference)
#include <cuda_runtime.h>
#include <cuda_bf16.h>
#include <math.h>

// Problem constants (fixed by the dataset)
#define B_ROWS   512
#define DIN      512
#define DDIM     256
#define NTRAIN   500000
#define NCLASS   1000
#define TOPK     7
#define CAP      4096
#define THRESH   3.0f
#define MARGIN   0.1f
#define NEGBIG  -1e30f

// Scratch (device globals: allocation-free rule)
__device__ float          g_z [B_ROWS * DDIM];
__device__ __nv_bfloat16  g_zb[B_ROWS * DDIM];
__device__ int            g_cnt [B_ROWS];
__device__ float          g_cval[B_ROWS * CAP];
__device__ int            g_cidx[B_ROWS * CAP];

static __device__ __forceinline__ unsigned smem_u32(const void* p) {
    return (unsigned)__cvta_generic_to_shared(p);
}
static __device__ __forceinline__ unsigned pack_bf16x2(float a, float b) {
    __nv_bfloat162 h = __floats2bfloat162_rn(a, b);
    return *reinterpret_cast<unsigned*>(&h);
}

#define LDSM4(R, ADDR) \
    asm volatile("ldmatrix.sync.aligned.m8n8.x4.shared.b16 {%0,%1,%2,%3}, [%4];" \
        : "=r"((R)[0]), "=r"((R)[1]), "=r"((R)[2]), "=r"((R)[3]) : "r"(ADDR))

#define MMA16816(D, A, B0, B1) \
    asm volatile("mma.sync.aligned.m16n8k16.row.col.f32.bf16.bf16.f32 " \
        "{%0,%1,%2,%3}, {%4,%5,%6,%7}, {%8,%9}, {%0,%1,%2,%3};" \
        : "+f"((D)[0]), "+f"((D)[1]), "+f"((D)[2]), "+f"((D)[3]) \
        : "r"((A)[0]), "r"((A)[1]), "r"((A)[2]), "r"((A)[3]), "r"(B0), "r"(B1))

// ---------------------------------------------------------------------------
// K1: preprocess -> z (fp32 + bf16), zero candidate counters
// block b (512 blocks), 256 threads (one per output dim)
// ---------------------------------------------------------------------------
__global__ __launch_bounds__(256) void k_prep(
    const float* __restrict__ x, const float* __restrict__ mean1,
    const float* __restrict__ std1, const float* __restrict__ P,
    const float* __restrict__ mean2, const float* __restrict__ std2)
{
    const int b = blockIdx.x;
    const int t = threadIdx.x;
    __shared__ float sx[DIN];
    __shared__ float red[256];

    for (int i = t; i < DIN; i += 256)
        sx[i] = (x[b * DIN + i] - mean1[i]) / std1[i];
    __syncthreads();

    float acc = 0.f;
    #pragma unroll 8
    for (int k = 0; k < DIN; k++)
        acc += sx[k] * P[k * DDIM + t];

    float z2 = (acc - mean2[t]) / std2[t];
    red[t] = z2 * z2;
    __syncthreads();
    for (int s = 128; s > 0; s >>= 1) {
        if (t < s) red[t] += red[t + s];
        __syncthreads();
    }
    float nrm = sqrtf(red[0]);
    float zv = z2 / fmaxf(nrm, 1e-12f);

    g_z [b * DDIM + t] = zv;
    g_zb[b * DDIM + t] = __float2bfloat16(zv);
    if (t == 0) g_cnt[b] = 0;
}

// ---------------------------------------------------------------------------
// K2: bf16 mma.sync GEMM (sims = z @ train^T) with fused candidate selection
// CTA: 256 M x 128 N, K = 256 in four 64-wide chunks.
// smem: A = 256x256 bf16 (swizzled, 131072 B), B chunk = 128x64 bf16 (16384 B)
// grid: x = m-block (2), y = n-block (3907) so the two M-halves of the same
//       train tile are adjacent in launch order -> train read once from DRAM,
//       second pass hits L2.
// ---------------------------------------------------------------------------
__global__ __launch_bounds__(256, 1) void k_gemm(const float* __restrict__ train)
{
    extern __shared__ char smem[];
    char* sA = smem;               // 131072 B
    char* sB = smem + 131072;      // 16384 B

    const int t    = threadIdx.x;
    const int lane = t & 31;
    const int warp = t >> 5;
    const int wm   = warp & 3;     // 4 warps along M (64 rows each)
    const int wn   = warp >> 2;    // 2 warps along N (64 cols each)
    const int m0   = blockIdx.x * 256;
    const int n0   = blockIdx.y * 128;

    // ---- load A tile (z bf16, 256x256) into swizzled smem ----
    // 256 rows x 32 chunks(16B) = 8192 uint4 -> 32 iterations of 256 threads
    #pragma unroll
    for (int i = 0; i < 32; i++) {
        int idx = t + i * 256;
        int row = idx >> 5, cb = idx & 31;
        uint4 v = *reinterpret_cast<const uint4*>(&g_zb[(m0 + row) * DDIM + cb * 8]);
        *reinterpret_cast<uint4*>(sA + row * 512 + ((cb ^ (row & 7)) << 4)) = v;
    }

    // ---- prefetch B chunk 0 into registers (fp32 -> bf16) ----
    uint4 ubuf[4];
    {
        const int c = 0;
        #pragma unroll
        for (int u = 0; u < 4; u++) {
            int idx = t + u * 256;
            int row = idx >> 3, cb = idx & 7;
            int gr = n0 + row;
            float4 f0 = make_float4(0.f, 0.f, 0.f, 0.f), f1 = f0;
            if (gr < NTRAIN) {
                const float4* p = reinterpret_cast<const float4*>(
                    train + (size_t)gr * DDIM + c * 64 + cb * 8);
                f0 = p[0]; f1 = p[1];
            }
            ubuf[u] = make_uint4(pack_bf16x2(f0.x, f0.y), pack_bf16x2(f0.z, f0.w),
                                 pack_bf16x2(f1.x, f1.y), pack_bf16x2(f1.z, f1.w));
        }
    }

    float acc[4][8][4];
    #pragma unroll
    for (int mi = 0; mi < 4; mi++)
        #pragma unroll
        for (int ni = 0; ni < 8; ni++)
            #pragma unroll
            for (int e = 0; e < 4; e++) acc[mi][ni][e] = 0.f;

    const int grp = lane >> 3, wl = lane & 7;

    for (int c = 0; c < 4; c++) {
        __syncthreads();   // A ready (c==0); previous compute done before B overwrite
        // store B chunk to swizzled smem
        #pragma unroll
        for (int u = 0; u < 4; u++) {
            int idx = t + u * 256;
            int row = idx >> 3, cb = idx & 7;
            *reinterpret_cast<uint4*>(sB + row * 128 + ((cb ^ (row & 7)) << 4)) = ubuf[u];
        }
        __syncthreads();

        // prefetch next chunk while computing this one
        if (c < 3) {
            const int cn = c + 1;
            #pragma unroll
            for (int u = 0; u < 4; u++) {
                int idx = t + u * 256;
                int row = idx >> 3, cb = idx & 7;
                int gr = n0 + row;
                float4 f0 = make_float4(0.f, 0.f, 0.f, 0.f), f1 = f0;
                if (gr < NTRAIN) {
                    const float4* p = reinterpret_cast<const float4*>(
                        train + (size_t)gr * DDIM + cn * 64 + cb * 8);
                    f0 = p[0]; f1 = p[1];
                }
                ubuf[u] = make_uint4(pack_bf16x2(f0.x, f0.y), pack_bf16x2(f0.z, f0.w),
                                     pack_bf16x2(f1.x, f1.y), pack_bf16x2(f1.z, f1.w));
            }
        }

        // compute: 4 k16-steps over this 64-wide chunk
        #pragma unroll
        for (int s = 0; s < 4; s++) {
            const int kcbA = (c << 3) + (s << 1);
            unsigned a_frag[4][4];
            #pragma unroll
            for (int mi = 0; mi < 4; mi++) {
                int arow = wm * 64 + mi * 16 + ((grp & 1) << 3) + wl;
                int acb  = kcbA + (grp >> 1);
                unsigned addr = smem_u32(sA + arow * 512 + ((acb ^ (arow & 7)) << 4));
                LDSM4(a_frag[mi], addr);
            }
            const int kcbB = s << 1;
            #pragma unroll
            for (int nb = 0; nb < 4; nb++) {
                int brow = wn * 64 + nb * 16 + ((grp & 2) << 2) + wl;
                int bcb  = kcbB + (grp & 1);
                unsigned addr = smem_u32(sB + brow * 128 + ((bcb ^ (brow & 7)) << 4));
                unsigned b_frag[4];
                LDSM4(b_frag, addr);
                #pragma unroll
                for (int mi = 0; mi < 4; mi++) {
                    MMA16816(acc[mi][nb * 2 + 0], a_frag[mi], b_frag[0], b_frag[1]);
                    MMA16816(acc[mi][nb * 2 + 1], a_frag[mi], b_frag[2], b_frag[3]);
                }
            }
        }
    }

    // ---- epilogue: threshold + append candidates ----
    const int mrow0 = m0 + wm * 64 + (lane >> 2);
    const int ncol0 = n0 + wn * 64 + (lane & 3) * 2;
    #pragma unroll
    for (int mi = 0; mi < 4; mi++) {
        #pragma unroll
        for (int ni = 0; ni < 8; ni++) {
            #pragma unroll
            for (int e = 0; e < 4; e++) {
                float v = acc[mi][ni][e];
                if (v > THRESH) {
                    int row = mrow0 + mi * 16 + ((e >> 1) << 3);
                    int col = ncol0 + ni * 8 + (e & 1);
                    if (col < NTRAIN) {
                        int p = atomicAdd(&g_cnt[row], 1);
                        if (p < CAP) {
                            g_cval[row * CAP + p] = v;
                            g_cidx[row * CAP + p] = col;
                        }
                    }
                }
            }
        }
    }
}

// ---------------------------------------------------------------------------
// K3: per-row shortlist -> exact fp32 rescore -> exact top-7 -> weighted scatter
// block b (512 blocks), 256 threads
// ---------------------------------------------------------------------------
__global__ __launch_bounds__(256) void k_final(
    const float* __restrict__ train, const int* __restrict__ labels,
    float* __restrict__ out)
{
    const int b = blockIdx.x;
    const int t = threadIdx.x;
    const int lane = t & 31, warp = t >> 5;

    __shared__ float sz[DDIM];
    __shared__ float stop[256 * 8];   // per-thread top-7 (padded stride 8)
    __shared__ float sex[256];
    __shared__ int   sxid[256];
    __shared__ int   s_n;
    __shared__ float s_a7;

    sz[t] = g_z[b * DDIM + t];
    int cnt = g_cnt[b];
    if (cnt > CAP) cnt = CAP;

    // per-thread top-7 of approximate values
    float tv[TOPK];
    #pragma unroll
    for (int k = 0; k < TOPK; k++) tv[k] = NEGBIG;
    for (int i = t; i < cnt; i += 256) {
        float v = g_cval[b * CAP + i];
        if (v > tv[TOPK - 1]) {
            int k = TOPK - 1;
            while (k > 0 && v > tv[k - 1]) { tv[k] = tv[k - 1]; k--; }
            tv[k] = v;
        }
    }
    #pragma unroll
    for (int k = 0; k < TOPK; k++) stop[t * 8 + k] = tv[k];
    if (t == 0) s_n = 0;
    __syncthreads();

    // warp 0: find 7th-largest approximate value (a7)
    if (warp == 0) {
        float a7 = NEGBIG;
        for (int p = 0; p < TOPK; p++) {
            float best = NEGBIG; int bi = -1;
            for (int i = lane; i < 256 * TOPK; i += 32) {
                int tt = i / TOPK, kk = i - tt * TOPK;
                float v = stop[tt * 8 + kk];
                if (v > best) { best = v; bi = tt * 8 + kk; }
            }
            #pragma unroll
            for (int o = 16; o > 0; o >>= 1) {
                float ov = __shfl_down_sync(0xffffffffu, best, o);
                int   oi = __shfl_down_sync(0xffffffffu, bi, o);
                if (ov > best) { best = ov; bi = oi; }
            }
            best = __shfl_sync(0xffffffffu, best, 0);
            bi   = __shfl_sync(0xffffffffu, bi, 0);
            if (lane == 0 && bi >= 0) stop[bi] = NEGBIG;
            __syncwarp();
            a7 = best;
        }
        if (lane == 0) s_a7 = a7;
    }
    __syncthreads();
    const float cut = s_a7 - MARGIN;

    // exact fp32 rescore of shortlisted candidates (one warp per candidate)
    for (int i = warp; i < cnt; i += 8) {
        float av = g_cval[b * CAP + i];
        if (av >= cut) {
            int idx = g_cidx[b * CAP + i];
            const float* tr = train + (size_t)idx * DDIM;
            float s = 0.f;
            #pragma unroll
            for (int j = 0; j < 8; j++)
                s += sz[j * 32 + lane] * tr[j * 32 + lane];
            #pragma unroll
            for (int o = 16; o > 0; o >>= 1)
                s += __shfl_down_sync(0xffffffffu, s, o);
            if (lane == 0) {
                int p = atomicAdd(&s_n, 1);
                if (p < 256) { sex[p] = s; sxid[p] = idx; }
            }
        }
    }
    __syncthreads();
    int m = s_n < 256 ? s_n : 256;

    // zero output row
    for (int i = t; i < NCLASS; i += 256) out[b * NCLASS + i] = 0.f;
    __syncthreads();

    // exact top-7 with jax tie-break (value desc, train index asc) + scatter
    if (t == 0) {
        float vsel[TOPK]; int isel[TOPK];
        for (int k = 0; k < TOPK; k++) {
            float bv = NEGBIG; int bidx = 0x7fffffff; int bp = -1;
            for (int i = 0; i < m; i++) {
                float v = sex[i]; int id = sxid[i];
                if (v > bv || (v == bv && id < bidx)) { bv = v; bidx = id; bp = i; }
            }
            vsel[k] = bv; isel[k] = bidx;
            if (bp >= 0) sex[bp] = NEGBIG;
        }
        float v0 = vsel[0];
        for (int k = 0; k < TOPK; k++) {
            if (vsel[k] <= -1e29f) break;
            float w = expf((vsel[k] - v0) / 0.07f);
            out[b * NCLASS + labels[isel[k]]] += w;
        }
    }
}

// ---------------------------------------------------------------------------
extern "C" void kernel_launch(void* const* d_in, const int* in_sizes, int n_in,
                              void* d_out, int out_size)
{
    const float* x     = (const float*)d_in[0];
    const float* mean1 = (const float*)d_in[1];
    const float* std1  = (const float*)d_in[2];
    const float* P     = (const float*)d_in[3];
    const float* mean2 = (const float*)d_in[4];
    const float* std2  = (const float*)d_in[5];
    const float* train = (const float*)d_in[6];
    const int*   lbl   = (const int*)d_in[7];
    float* out = (float*)d_out;

    (void)in_sizes; (void)n_in; (void)out_size;

    const int smem_bytes = 131072 + 16384;
    cudaFuncSetAttribute(k_gemm, cudaFuncAttributeMaxDynamicSharedMemorySize, smem_bytes);

    k_prep<<<B_ROWS, 256>>>(x, mean1, std1, P, mean2, std2);
    dim3 grid(2, (NTRAIN + 127) / 128);   // m-blocks adjacent -> train tile L2 reuse
    k_gemm<<<grid, 256, smem_bytes>>>(train);
    k_final<<<B_ROWS, 256>>>(train, lbl, out);
}

// round 16
// speedup vs baseline: 1.1025x; 1.1025x over previous
#include <cuda_runtime.h>
#include <cuda_bf16.h>
#include <math.h>
#include <stdint.h>

// Problem constants
#define B_ROWS   512
#define DIN      512
#define DDIM     256
#define NTRAIN   500000
#define NCLASS   1000
#define TOPK     7
#define CAP      4096
#define THRESH   3.0f
#define MARGIN   0.1f
#define NEGBIG  -1e30f

#define NT       128                         // N per tile
#define NTILES   ((NTRAIN + NT - 1) / NT)    // 3907
#define NSTREAMS 74                          // n-streams; x2 mgroups = 148 CTAs
#define RING     4                           // B-stage ring depth

// Scratch (device globals: allocation-free rule)
__device__ float          g_z [B_ROWS * DDIM];
__device__ __nv_bfloat16  g_zb[B_ROWS * DDIM];
__device__ int            g_cnt [B_ROWS];
__device__ float          g_cval[B_ROWS * CAP];
__device__ int            g_cidx[B_ROWS * CAP];

static __device__ __forceinline__ unsigned smem_u32(const void* p) {
    return (unsigned)__cvta_generic_to_shared(p);
}
static __device__ __forceinline__ unsigned pack_bf16x2(float a, float b) {
    __nv_bfloat162 h = __floats2bfloat162_rn(a, b);
    return *reinterpret_cast<unsigned*>(&h);
}
static __device__ __forceinline__ uint32_t sw128(uint32_t off) {
    return off ^ ((off >> 3) & 0x70);
}

// ---- mbarrier helpers (baseline PTX, sm_90+, no arch-specific features) ----
#define MBARRIER_INIT(mbar, count) \
    asm volatile("mbarrier.init.shared.b64 [%0], %1;" \
        :: "r"((uint32_t)(mbar)), "r"((uint32_t)(count)) : "memory")

#define MBARRIER_ARRIVE(mbar) \
    asm volatile("mbarrier.arrive.release.cta.shared::cta.b64 _, [%0];" \
        :: "r"((uint32_t)(mbar)) : "memory")

#define MBARRIER_WAIT_PARITY(mbar, parity) do { \
    uint32_t _mbar = (uint32_t)(mbar); \
    uint32_t _par  = (uint32_t)(parity); \
    uint32_t _done; \
    asm volatile( \
        "{\n\t.reg .pred p;\n\t" \
        "mbarrier.try_wait.parity.acquire.cta.shared::cta.b64 p, [%1], %2;\n\t" \
        "selp.b32 %0, 1, 0, p;\n\t}" \
        : "=r"(_done) : "r"(_mbar), "r"(_par) : "memory"); \
    if (!_done) { \
        asm volatile( \
            "{\n\t.reg .pred P1;\n\t" \
            "WAIT_LOOP_%=:\n\t" \
            "mbarrier.try_wait.parity.acquire.cta.shared::cta.b64 P1, [%0], %1, 0x989680;\n\t" \
            "@P1 bra.uni WAIT_DONE_%=;\n\t" \
            "bra.uni WAIT_LOOP_%=;\n\t" \
            "WAIT_DONE_%=:\n\t}" \
            :: "r"(_mbar), "r"(_par) : "memory"); \
    } \
} while (0)

#define LDSM4(R, ADDR) \
    asm volatile("ldmatrix.sync.aligned.m8n8.x4.shared.b16 {%0,%1,%2,%3}, [%4];" \
        : "=r"((R)[0]), "=r"((R)[1]), "=r"((R)[2]), "=r"((R)[3]) : "r"(ADDR))

#define MMA16816(D, A, B0, B1) \
    asm volatile("mma.sync.aligned.m16n8k16.row.col.f32.bf16.bf16.f32 " \
        "{%0,%1,%2,%3}, {%4,%5,%6,%7}, {%8,%9}, {%0,%1,%2,%3};" \
        : "+f"((D)[0]), "+f"((D)[1]), "+f"((D)[2]), "+f"((D)[3]) \
        : "r"((A)[0]), "r"((A)[1]), "r"((A)[2]), "r"((A)[3]), "r"(B0), "r"(B1))

// ---------------------------------------------------------------------------
// K1: preprocess -> z (fp32 + bf16). 64 blocks x 8 batch-rows.
// ---------------------------------------------------------------------------
__global__ __launch_bounds__(256) void k_prep(
    const float* __restrict__ x, const float* __restrict__ mean1,
    const float* __restrict__ std1, const float* __restrict__ P,
    const float* __restrict__ mean2, const float* __restrict__ std2)
{
    const int b0 = blockIdx.x * 8;
    const int t  = threadIdx.x;
    __shared__ float sx[8][DIN];
    __shared__ float red[256];

    for (int i = t; i < 8 * DIN; i += 256) {
        int r = i >> 9, k = i & 511;
        sx[r][k] = (x[(b0 + r) * DIN + k] - mean1[k]) / std1[k];
    }
    __syncthreads();

    float acc[8];
    #pragma unroll
    for (int r = 0; r < 8; r++) acc[r] = 0.f;
    #pragma unroll 4
    for (int k = 0; k < DIN; k++) {
        float pk = P[k * DDIM + t];
        #pragma unroll
        for (int r = 0; r < 8; r++) acc[r] += sx[r][k] * pk;
    }

    const float m2 = mean2[t], s2 = std2[t];
    for (int r = 0; r < 8; r++) {
        float v = (acc[r] - m2) / s2;
        red[t] = v * v;
        __syncthreads();
        for (int s = 128; s > 0; s >>= 1) {
            if (t < s) red[t] += red[t + s];
            __syncthreads();
        }
        float zv = v / fmaxf(sqrtf(red[0]), 1e-12f);
        __syncthreads();
        g_z [(b0 + r) * DDIM + t] = zv;
        g_zb[(b0 + r) * DDIM + t] = __float2bfloat16(zv);
    }
    if (blockIdx.x == 0) { g_cnt[t] = 0; g_cnt[256 + t] = 0; }
}

// ---------------------------------------------------------------------------
// K2: persistent warp-specialized bf16 mma.sync GEMM.
// 148 CTAs = 2 mgroups x 74 streams. CTA tile: 256 M (A resident) x 128 N.
// Warps 0-7: consumers (64x64 warp tiles, ldmatrix+mma, epilogue threshold).
// Warps 8-9: producers (train fp32 -> bf16 -> swizzled smem ring, 4 stages).
// smem: ctrl(RING mbarrier pairs) | A 128KB | B ring 4 x 16KB.
// ---------------------------------------------------------------------------
#define SM_A      1024
#define SM_B      (SM_A + 131072)
#define SM_TOTAL  (SM_B + RING * 16384)

__global__ __launch_bounds__(320, 1) void k_gemm_ws(const float* __restrict__ train)
{
    extern __shared__ char dsm[];
    const uint32_t raw   = smem_u32(dsm);
    const uint32_t sbase = (raw + 1023u) & ~1023u;
    const uint32_t ctrl  = sbase;                 // RING x {full,empty} 8B pairs
    const uint32_t sA    = sbase + SM_A;

    const int t      = threadIdx.x;
    const int warp   = t >> 5;
    const int lane   = t & 31;
    const int mgroup = blockIdx.x / NSTREAMS;     // 0 or 1
    const int stream = blockIdx.x % NSTREAMS;
    const int m0     = mgroup * 256;

    if (t == 0) {
        #pragma unroll
        for (int s = 0; s < RING; s++) {
            MBARRIER_INIT(ctrl + s * 16,     64);   // full: 2 producer warps
            MBARRIER_INIT(ctrl + s * 16 + 8, 256);  // empty: 8 consumer warps
        }
    }

    // ---- load resident A tile (256 rows x 256 K bf16, swizzled) ----
    for (int u = t; u < 8192; u += 320) {
        int row = u >> 5, cb = u & 31;
        uint4 v = *reinterpret_cast<const uint4*>(&g_zb[(m0 + row) * DDIM + cb * 8]);
        *reinterpret_cast<uint4*>(dsm + (sA - raw) + row * 512 + ((cb ^ (row & 7)) << 4)) = v;
    }
    __syncthreads();

    if (warp >= 8) {
        // ====================== PRODUCERS (64 threads) ======================
        const int l = t - 256;
        int slot = 0, pph = 1;                    // first empty-wait passes
        for (int i = stream; i < NTILES; i += NSTREAMS) {
            const int n0 = i * NT;
            for (int c = 0; c < 4; c++) {
                MBARRIER_WAIT_PARITY(ctrl + slot * 16 + 8, pph);
                const uint32_t dst = sbase + SM_B + slot * 16384 - raw;
                #pragma unroll
                for (int u0 = 0; u0 < 16; u0++) {
                    int u = l + u0 * 64;          // 1024 16B-chunks per stage
                    int row = u >> 3, kc = u & 7;
                    int gr = n0 + row;
                    float4 f0 = make_float4(0.f,0.f,0.f,0.f), f1 = f0;
                    if (gr < NTRAIN) {
                        const float4* sp = reinterpret_cast<const float4*>(
                            train + (size_t)gr * DDIM + c * 64 + kc * 8);
                        f0 = sp[0]; f1 = sp[1];
                    }
                    uint4 v = make_uint4(pack_bf16x2(f0.x,f0.y), pack_bf16x2(f0.z,f0.w),
                                         pack_bf16x2(f1.x,f1.y), pack_bf16x2(f1.z,f1.w));
                    *reinterpret_cast<uint4*>(dsm + dst + sw128(row * 128 + kc * 16)) = v;
                }
                MBARRIER_ARRIVE(ctrl + slot * 16);
                if (++slot == RING) { slot = 0; pph ^= 1; }
            }
        }
    } else {
        // ====================== CONSUMERS (256 threads) ======================
        const int wm  = warp & 3;                 // 4 warps along M
        const int wn  = warp >> 2;                // 2 warps along N
        const int grp = lane >> 3, wl = lane & 7;
        int slot = 0, cph = 0;

        for (int i = stream; i < NTILES; i += NSTREAMS) {
            const int n0 = i * NT;
            float acc[4][8][4];
            #pragma unroll
            for (int mi = 0; mi < 4; mi++)
                #pragma unroll
                for (int ni = 0; ni < 8; ni++)
                    #pragma unroll
                    for (int e = 0; e < 4; e++) acc[mi][ni][e] = 0.f;

            for (int c = 0; c < 4; c++) {
                MBARRIER_WAIT_PARITY(ctrl + slot * 16, cph);
                const uint32_t sB = sbase + SM_B + slot * 16384;
                #pragma unroll
                for (int s = 0; s < 4; s++) {
                    const int kcbA = (c << 3) + (s << 1);
                    unsigned a_frag[4][4];
                    #pragma unroll
                    for (int mi = 0; mi < 4; mi++) {
                        int arow = wm * 64 + mi * 16 + ((grp & 1) << 3) + wl;
                        int acb  = kcbA + (grp >> 1);
                        LDSM4(a_frag[mi], sA + arow * 512 + ((acb ^ (arow & 7)) << 4));
                    }
                    const int kcbB = s << 1;
                    #pragma unroll
                    for (int nb = 0; nb < 4; nb++) {
                        int brow = wn * 64 + nb * 16 + ((grp & 2) << 2) + wl;
                        int bcb  = kcbB + (grp & 1);
                        unsigned b_frag[4];
                        LDSM4(b_frag, sB + brow * 128 + ((bcb ^ (brow & 7)) << 4));
                        #pragma unroll
                        for (int mi = 0; mi < 4; mi++) {
                            MMA16816(acc[mi][nb * 2 + 0], a_frag[mi], b_frag[0], b_frag[1]);
                            MMA16816(acc[mi][nb * 2 + 1], a_frag[mi], b_frag[2], b_frag[3]);
                        }
                    }
                }
                MBARRIER_ARRIVE(ctrl + slot * 16 + 8);
                if (++slot == RING) { slot = 0; cph ^= 1; }
            }

            // epilogue: threshold + candidate append
            const int mrow0 = m0 + wm * 64 + (lane >> 2);
            const int ncol0 = n0 + wn * 64 + (lane & 3) * 2;
            #pragma unroll
            for (int mi = 0; mi < 4; mi++) {
                #pragma unroll
                for (int ni = 0; ni < 8; ni++) {
                    #pragma unroll
                    for (int e = 0; e < 4; e++) {
                        float v = acc[mi][ni][e];
                        if (v > THRESH) {
                            int row = mrow0 + mi * 16 + ((e >> 1) << 3);
                            int col = ncol0 + ni * 8 + (e & 1);
                            if (col < NTRAIN) {
                                int p = atomicAdd(&g_cnt[row], 1);
                                if (p < CAP) {
                                    g_cval[row * CAP + p] = v;
                                    g_cidx[row * CAP + p] = col;
                                }
                            }
                        }
                    }
                }
            }
        }
    }
}

// ---------------------------------------------------------------------------
// K3: per-row shortlist -> exact fp32 rescore -> exact top-7 -> weighted scatter
// ---------------------------------------------------------------------------
__global__ __launch_bounds__(256) void k_final(
    const float* __restrict__ train, const int* __restrict__ labels,
    float* __restrict__ out)
{
    const int b = blockIdx.x;
    const int t = threadIdx.x;
    const int lane = t & 31, warp = t >> 5;

    __shared__ float sz[DDIM];
    __shared__ float stop[256 * 8];
    __shared__ float sex[256];
    __shared__ int   sxid[256];
    __shared__ int   s_n;
    __shared__ float s_a7;

    sz[t] = g_z[b * DDIM + t];
    int cnt = g_cnt[b];
    if (cnt > CAP) cnt = CAP;

    float tv[TOPK];
    #pragma unroll
    for (int k = 0; k < TOPK; k++) tv[k] = NEGBIG;
    for (int i = t; i < cnt; i += 256) {
        float v = g_cval[b * CAP + i];
        if (v > tv[TOPK - 1]) {
            int k = TOPK - 1;
            while (k > 0 && v > tv[k - 1]) { tv[k] = tv[k - 1]; k--; }
            tv[k] = v;
        }
    }
    #pragma unroll
    for (int k = 0; k < TOPK; k++) stop[t * 8 + k] = tv[k];
    if (t == 0) s_n = 0;
    __syncthreads();

    if (warp == 0) {
        float a7 = NEGBIG;
        for (int p = 0; p < TOPK; p++) {
            float best = NEGBIG; int bi = -1;
            for (int i = lane; i < 256 * TOPK; i += 32) {
                int tt = i / TOPK, kk = i - tt * TOPK;
                float v = stop[tt * 8 + kk];
                if (v > best) { best = v; bi = tt * 8 + kk; }
            }
            #pragma unroll
            for (int o = 16; o > 0; o >>= 1) {
                float ov = __shfl_down_sync(0xffffffffu, best, o);
                int   oi = __shfl_down_sync(0xffffffffu, bi, o);
                if (ov > best) { best = ov; bi = oi; }
            }
            best = __shfl_sync(0xffffffffu, best, 0);
            bi   = __shfl_sync(0xffffffffu, bi, 0);
            if (lane == 0 && bi >= 0) stop[bi] = NEGBIG;
            __syncwarp();
            a7 = best;
        }
        if (lane == 0) s_a7 = a7;
    }
    __syncthreads();
    const float cut = s_a7 - MARGIN;

    for (int i = warp; i < cnt; i += 8) {
        float av = g_cval[b * CAP + i];
        if (av >= cut) {
            int idx = g_cidx[b * CAP + i];
            const float* tr = train + (size_t)idx * DDIM;
            float s = 0.f;
            #pragma unroll
            for (int j = 0; j < 8; j++)
                s += sz[j * 32 + lane] * tr[j * 32 + lane];
            #pragma unroll
            for (int o = 16; o > 0; o >>= 1)
                s += __shfl_down_sync(0xffffffffu, s, o);
            if (lane == 0) {
                int p = atomicAdd(&s_n, 1);
                if (p < 256) { sex[p] = s; sxid[p] = idx; }
            }
        }
    }
    __syncthreads();
    int m = s_n < 256 ? s_n : 256;

    for (int i = t; i < NCLASS; i += 256) out[b * NCLASS + i] = 0.f;
    __syncthreads();

    if (t == 0) {
        float vsel[TOPK]; int isel[TOPK];
        for (int k = 0; k < TOPK; k++) {
            float bv = NEGBIG; int bidx = 0x7fffffff; int bp = -1;
            for (int i = 0; i < m; i++) {
                float v = sex[i]; int id = sxid[i];
                if (v > bv || (v == bv && id < bidx)) { bv = v; bidx = id; bp = i; }
            }
            vsel[k] = bv; isel[k] = bidx;
            if (bp >= 0) sex[bp] = NEGBIG;
        }
        float v0 = vsel[0];
        for (int k = 0; k < TOPK; k++) {
            if (vsel[k] <= -1e29f) break;
            float w = expf((vsel[k] - v0) / 0.07f);
            out[b * NCLASS + labels[isel[k]]] += w;
        }
    }
}

// ---------------------------------------------------------------------------
extern "C" void kernel_launch(void* const* d_in, const int* in_sizes, int n_in,
                              void* d_out, int out_size)
{
    const float* x     = (const float*)d_in[0];
    const float* mean1 = (const float*)d_in[1];
    const float* std1  = (const float*)d_in[2];
    const float* P     = (const float*)d_in[3];
    const float* mean2 = (const float*)d_in[4];
    const float* std2  = (const float*)d_in[5];
    const float* train = (const float*)d_in[6];
    const int*   lbl   = (const int*)d_in[7];
    float* out = (float*)d_out;

    (void)in_sizes; (void)n_in; (void)out_size;

    const int smem_bytes = SM_TOTAL + 1024;   // + alignment slack
    cudaFuncSetAttribute(k_gemm_ws, cudaFuncAttributeMaxDynamicSharedMemorySize, smem_bytes);

    k_prep<<<B_ROWS / 8, 256>>>(x, mean1, std1, P, mean2, std2);
    k_gemm_ws<<<2 * NSTREAMS, 320, smem_bytes>>>(train);
    k_final<<<B_ROWS, 256>>>(train, lbl, out);
}

// round 17
// speedup vs baseline: 1.1682x; 1.0597x over previous
#include <cuda_runtime.h>
#include <cuda_bf16.h>
#include <math.h>
#include <stdint.h>

// Problem constants
#define B_ROWS   512
#define DIN      512
#define DDIM     256
#define NTRAIN   500000
#define NCLASS   1000
#define TOPK     7
#define CAP      4096
#define THRESH   3.0f
#define MARGIN   0.1f
#define NEGBIG  -1e30f

#define NT       128                         // N per tile
#define NTILES   ((NTRAIN + NT - 1) / NT)    // 3907
#define NSTREAMS 74                          // n-streams; x2 mgroups = 148 CTAs
#define RING     4                           // B-stage ring depth
#define STAGE_B  16384                       // bytes per B stage (128N x 64K bf16)

// Scratch (device globals: allocation-free rule)
__device__ float          g_z [B_ROWS * DDIM];
__device__ __nv_bfloat16  g_zb[B_ROWS * DDIM];
__device__ int            g_cnt [B_ROWS];
__device__ float          g_cval[B_ROWS * CAP];
__device__ int            g_cidx[B_ROWS * CAP];
// pre-converted, pre-swizzled train: NTILES x 4 stages x 16KB smem images (256 MB)
__device__ __align__(16) unsigned char g_tb[NTILES * 4 * STAGE_B];

static __device__ __forceinline__ unsigned smem_u32(const void* p) {
    return (unsigned)__cvta_generic_to_shared(p);
}
static __device__ __forceinline__ unsigned pack_bf16x2(float a, float b) {
    __nv_bfloat162 h = __floats2bfloat162_rn(a, b);
    return *reinterpret_cast<unsigned*>(&h);
}
static __device__ __forceinline__ uint32_t sw128(uint32_t off) {
    return off ^ ((off >> 3) & 0x70);
}

// ---- mbarrier / bulk-copy helpers (baseline PTX, sm_90+) ----
#define MBARRIER_INIT(mbar, count) \
    asm volatile("mbarrier.init.shared.b64 [%0], %1;" \
        :: "r"((uint32_t)(mbar)), "r"((uint32_t)(count)) : "memory")

#define MBARRIER_ARRIVE(mbar) \
    asm volatile("mbarrier.arrive.release.cta.shared::cta.b64 _, [%0];" \
        :: "r"((uint32_t)(mbar)) : "memory")

#define MBARRIER_EXPECT_TX(mbar, bytes) \
    asm volatile("mbarrier.arrive.expect_tx.shared.b64 _, [%0], %1;" \
        :: "r"((uint32_t)(mbar)), "r"((uint32_t)(bytes)) : "memory")

#define BULK_G2S(dst, src, bytes, mbar) \
    asm volatile("cp.async.bulk.shared::cluster.global.mbarrier::complete_tx::bytes " \
        "[%0], [%1], %2, [%3];" \
        :: "r"((uint32_t)(dst)), "l"(src), "r"((uint32_t)(bytes)), \
           "r"((uint32_t)(mbar)) : "memory")

#define MBARRIER_WAIT_PARITY(mbar, parity) do { \
    uint32_t _mbar = (uint32_t)(mbar); \
    uint32_t _par  = (uint32_t)(parity); \
    uint32_t _done; \
    asm volatile( \
        "{\n\t.reg .pred p;\n\t" \
        "mbarrier.try_wait.parity.acquire.cta.shared::cta.b64 p, [%1], %2;\n\t" \
        "selp.b32 %0, 1, 0, p;\n\t}" \
        : "=r"(_done) : "r"(_mbar), "r"(_par) : "memory"); \
    if (!_done) { \
        asm volatile( \
            "{\n\t.reg .pred P1;\n\t" \
            "WAIT_LOOP_%=:\n\t" \
            "mbarrier.try_wait.parity.acquire.cta.shared::cta.b64 P1, [%0], %1, 0x989680;\n\t" \
            "@P1 bra.uni WAIT_DONE_%=;\n\t" \
            "bra.uni WAIT_LOOP_%=;\n\t" \
            "WAIT_DONE_%=:\n\t}" \
            :: "r"(_mbar), "r"(_par) : "memory"); \
    } \
} while (0)

#define LDSM4(R, ADDR) \
    asm volatile("ldmatrix.sync.aligned.m8n8.x4.shared.b16 {%0,%1,%2,%3}, [%4];" \
        : "=r"((R)[0]), "=r"((R)[1]), "=r"((R)[2]), "=r"((R)[3]) : "r"(ADDR))

#define MMA16816(D, A, B0, B1) \
    asm volatile("mma.sync.aligned.m16n8k16.row.col.f32.bf16.bf16.f32 " \
        "{%0,%1,%2,%3}, {%4,%5,%6,%7}, {%8,%9}, {%0,%1,%2,%3};" \
        : "+f"((D)[0]), "+f"((D)[1]), "+f"((D)[2]), "+f"((D)[3]) \
        : "r"((A)[0]), "r"((A)[1]), "r"((A)[2]), "r"((A)[3]), "r"(B0), "r"(B1))

// ---------------------------------------------------------------------------
// K0: convert train fp32 -> bf16 with the per-stage swizzled smem image baked
// in. One block per n-tile; 4096 16B-chunks per tile (4 stages x 1024).
// ---------------------------------------------------------------------------
__global__ __launch_bounds__(256) void k_conv(const float* __restrict__ train)
{
    const int tile = blockIdx.x;
    const int t    = threadIdx.x;
    unsigned char* dst = g_tb + (size_t)tile * 4 * STAGE_B;

    for (int u = t; u < 4096; u += 256) {
        int c   = u >> 10;          // stage (K chunk of 64)
        int rem = u & 1023;
        int row = rem >> 3;         // 0..127 (train row within tile)
        int kc  = rem & 7;          // 16B chunk within 64 K cols
        int gr  = tile * NT + row;
        float4 f0 = make_float4(0.f,0.f,0.f,0.f), f1 = f0;
        if (gr < NTRAIN) {
            const float4* sp = reinterpret_cast<const float4*>(
                train + (size_t)gr * DDIM + c * 64 + kc * 8);
            f0 = sp[0]; f1 = sp[1];
        }
        uint4 v = make_uint4(pack_bf16x2(f0.x,f0.y), pack_bf16x2(f0.z,f0.w),
                             pack_bf16x2(f1.x,f1.y), pack_bf16x2(f1.z,f1.w));
        *reinterpret_cast<uint4*>(dst + (size_t)c * STAGE_B
                                  + sw128(row * 128 + kc * 16)) = v;
    }
}

// ---------------------------------------------------------------------------
// K1: preprocess -> z (fp32 + bf16). 256 blocks x 2 batch-rows.
// ---------------------------------------------------------------------------
__global__ __launch_bounds__(256) void k_prep(
    const float* __restrict__ x, const float* __restrict__ mean1,
    const float* __restrict__ std1, const float* __restrict__ P,
    const float* __restrict__ mean2, const float* __restrict__ std2)
{
    const int b0 = blockIdx.x * 2;
    const int t  = threadIdx.x;
    __shared__ float sx[2][DIN];
    __shared__ float red[256];

    for (int i = t; i < 2 * DIN; i += 256) {
        int r = i >> 9, k = i & 511;
        sx[r][k] = (x[(b0 + r) * DIN + k] - mean1[k]) / std1[k];
    }
    __syncthreads();

    float a0 = 0.f, a1 = 0.f;
    #pragma unroll 8
    for (int k = 0; k < DIN; k++) {
        float pk = P[k * DDIM + t];
        a0 += sx[0][k] * pk;
        a1 += sx[1][k] * pk;
    }

    const float m2 = mean2[t], s2 = std2[t];
    float vr[2] = { (a0 - m2) / s2, (a1 - m2) / s2 };
    for (int r = 0; r < 2; r++) {
        red[t] = vr[r] * vr[r];
        __syncthreads();
        for (int s = 128; s > 0; s >>= 1) {
            if (t < s) red[t] += red[t + s];
            __syncthreads();
        }
        float zv = vr[r] / fmaxf(sqrtf(red[0]), 1e-12f);
        __syncthreads();
        g_z [(b0 + r) * DDIM + t] = zv;
        g_zb[(b0 + r) * DDIM + t] = __float2bfloat16(zv);
    }
    if (blockIdx.x == 0) { g_cnt[t] = 0; g_cnt[256 + t] = 0; }
}

// ---------------------------------------------------------------------------
// K2: persistent warp-specialized bf16 mma.sync GEMM.
// 148 CTAs = 2 mgroups x 74 streams. CTA tile: 256 M (A resident) x 128 N.
// Warps 0-7: consumers (64x64 warp tiles). Warp 8 lane 0: producer issuing
// one cp.async.bulk (UBLKCP) of a pre-swizzled 16KB stage per ring slot.
// smem: ctrl(RING full/empty mbarrier pairs) | A 128KB | B ring 4 x 16KB.
// ---------------------------------------------------------------------------
#define SM_A      1024
#define SM_B      (SM_A + 131072)
#define SM_TOTAL  (SM_B + RING * STAGE_B)

__global__ __launch_bounds__(288, 1) void k_gemm_ws(const float* __restrict__ train)
{
    extern __shared__ char dsm[];
    const uint32_t raw   = smem_u32(dsm);
    const uint32_t sbase = (raw + 1023u) & ~1023u;
    const uint32_t ctrl  = sbase;                 // RING x {full,empty} 8B pairs
    const uint32_t sA    = sbase + SM_A;

    const int t      = threadIdx.x;
    const int warp   = t >> 5;
    const int lane   = t & 31;
    const int mgroup = blockIdx.x / NSTREAMS;     // 0 or 1
    const int stream = blockIdx.x % NSTREAMS;
    const int m0     = mgroup * 256;

    if (t == 0) {
        #pragma unroll
        for (int s = 0; s < RING; s++) {
            MBARRIER_INIT(ctrl + s * 16,     1);    // full: producer arrive + tx
            MBARRIER_INIT(ctrl + s * 16 + 8, 256);  // empty: 8 consumer warps
        }
    }

    // ---- load resident A tile (256 rows x 256 K bf16, swizzled) ----
    for (int u = t; u < 8192; u += 288) {
        int row = u >> 5, cb = u & 31;
        uint4 v = *reinterpret_cast<const uint4*>(&g_zb[(m0 + row) * DDIM + cb * 8]);
        *reinterpret_cast<uint4*>(dsm + (sA - raw) + row * 512 + ((cb ^ (row & 7)) << 4)) = v;
    }
    __syncthreads();

    if (warp == 8) {
        // ====================== PRODUCER (1 thread) ======================
        if (lane == 0) {
            int slot = 0, pph = 1;                // first empty-wait passes
            for (int i = stream; i < NTILES; i += NSTREAMS) {
                const unsigned char* src = g_tb + (size_t)i * 4 * STAGE_B;
                for (int c = 0; c < 4; c++) {
                    MBARRIER_WAIT_PARITY(ctrl + slot * 16 + 8, pph);
                    const uint32_t full = ctrl + slot * 16;
                    MBARRIER_EXPECT_TX(full, STAGE_B);
                    BULK_G2S(sbase + SM_B + slot * STAGE_B,
                             src + (size_t)c * STAGE_B, STAGE_B, full);
                    if (++slot == RING) { slot = 0; pph ^= 1; }
                }
            }
        }
    } else {
        // ====================== CONSUMERS (256 threads) ======================
        const int wm  = warp & 3;                 // 4 warps along M
        const int wn  = warp >> 2;                // 2 warps along N
        const int grp = lane >> 3, wl = lane & 7;
        int slot = 0, cph = 0;

        for (int i = stream; i < NTILES; i += NSTREAMS) {
            const int n0 = i * NT;
            float acc[4][8][4];
            #pragma unroll
            for (int mi = 0; mi < 4; mi++)
                #pragma unroll
                for (int ni = 0; ni < 8; ni++)
                    #pragma unroll
                    for (int e = 0; e < 4; e++) acc[mi][ni][e] = 0.f;

            for (int c = 0; c < 4; c++) {
                MBARRIER_WAIT_PARITY(ctrl + slot * 16, cph);
                const uint32_t sB = sbase + SM_B + slot * STAGE_B;
                #pragma unroll
                for (int s = 0; s < 4; s++) {
                    const int kcbA = (c << 3) + (s << 1);
                    unsigned a_frag[4][4];
                    #pragma unroll
                    for (int mi = 0; mi < 4; mi++) {
                        int arow = wm * 64 + mi * 16 + ((grp & 1) << 3) + wl;
                        int acb  = kcbA + (grp >> 1);
                        LDSM4(a_frag[mi], sA + arow * 512 + ((acb ^ (arow & 7)) << 4));
                    }
                    const int kcbB = s << 1;
                    #pragma unroll
                    for (int nb = 0; nb < 4; nb++) {
                        int brow = wn * 64 + nb * 16 + ((grp & 2) << 2) + wl;
                        int bcb  = kcbB + (grp & 1);
                        unsigned b_frag[4];
                        LDSM4(b_frag, sB + brow * 128 + ((bcb ^ (brow & 7)) << 4));
                        #pragma unroll
                        for (int mi = 0; mi < 4; mi++) {
                            MMA16816(acc[mi][nb * 2 + 0], a_frag[mi], b_frag[0], b_frag[1]);
                            MMA16816(acc[mi][nb * 2 + 1], a_frag[mi], b_frag[2], b_frag[3]);
                        }
                    }
                }
                MBARRIER_ARRIVE(ctrl + slot * 16 + 8);
                if (++slot == RING) { slot = 0; cph ^= 1; }
            }

            // epilogue: threshold + candidate append
            const int mrow0 = m0 + wm * 64 + (lane >> 2);
            const int ncol0 = n0 + wn * 64 + (lane & 3) * 2;
            #pragma unroll
            for (int mi = 0; mi < 4; mi++) {
                #pragma unroll
                for (int ni = 0; ni < 8; ni++) {
                    #pragma unroll
                    for (int e = 0; e < 4; e++) {
                        float v = acc[mi][ni][e];
                        if (v > THRESH) {
                            int row = mrow0 + mi * 16 + ((e >> 1) << 3);
                            int col = ncol0 + ni * 8 + (e & 1);
                            if (col < NTRAIN) {
                                int p = atomicAdd(&g_cnt[row], 1);
                                if (p < CAP) {
                                    g_cval[row * CAP + p] = v;
                                    g_cidx[row * CAP + p] = col;
                                }
                            }
                        }
                    }
                }
            }
        }
    }
    (void)train;
}

// ---------------------------------------------------------------------------
// K3: per-row shortlist -> exact fp32 rescore -> exact top-7 -> weighted scatter
// ---------------------------------------------------------------------------
__global__ __launch_bounds__(256) void k_final(
    const float* __restrict__ train, const int* __restrict__ labels,
    float* __restrict__ out)
{
    const int b = blockIdx.x;
    const int t = threadIdx.x;
    const int lane = t & 31, warp = t >> 5;

    __shared__ float sz[DDIM];
    __shared__ float stop[256 * 8];
    __shared__ float sex[256];
    __shared__ int   sxid[256];
    __shared__ int   s_n;
    __shared__ float s_a7;

    sz[t] = g_z[b * DDIM + t];
    int cnt = g_cnt[b];
    if (cnt > CAP) cnt = CAP;

    float tv[TOPK];
    #pragma unroll
    for (int k = 0; k < TOPK; k++) tv[k] = NEGBIG;
    for (int i = t; i < cnt; i += 256) {
        float v = g_cval[b * CAP + i];
        if (v > tv[TOPK - 1]) {
            int k = TOPK - 1;
            while (k > 0 && v > tv[k - 1]) { tv[k] = tv[k - 1]; k--; }
            tv[k] = v;
        }
    }
    #pragma unroll
    for (int k = 0; k < TOPK; k++) stop[t * 8 + k] = tv[k];
    if (t == 0) s_n = 0;
    __syncthreads();

    if (warp == 0) {
        float a7 = NEGBIG;
        for (int p = 0; p < TOPK; p++) {
            float best = NEGBIG; int bi = -1;
            for (int i = lane; i < 256 * TOPK; i += 32) {
                int tt = i / TOPK, kk = i - tt * TOPK;
                float v = stop[tt * 8 + kk];
                if (v > best) { best = v; bi = tt * 8 + kk; }
            }
            #pragma unroll
            for (int o = 16; o > 0; o >>= 1) {
                float ov = __shfl_down_sync(0xffffffffu, best, o);
                int   oi = __shfl_down_sync(0xffffffffu, bi, o);
                if (ov > best) { best = ov; bi = oi; }
            }
            best = __shfl_sync(0xffffffffu, best, 0);
            bi   = __shfl_sync(0xffffffffu, bi, 0);
            if (lane == 0 && bi >= 0) stop[bi] = NEGBIG;
            __syncwarp();
            a7 = best;
        }
        if (lane == 0) s_a7 = a7;
    }
    __syncthreads();
    const float cut = s_a7 - MARGIN;

    for (int i = warp; i < cnt; i += 8) {
        float av = g_cval[b * CAP + i];
        if (av >= cut) {
            int idx = g_cidx[b * CAP + i];
            const float* tr = train + (size_t)idx * DDIM;
            float s = 0.f;
            #pragma unroll
            for (int j = 0; j < 8; j++)
                s += sz[j * 32 + lane] * tr[j * 32 + lane];
            #pragma unroll
            for (int o = 16; o > 0; o >>= 1)
                s += __shfl_down_sync(0xffffffffu, s, o);
            if (lane == 0) {
                int p = atomicAdd(&s_n, 1);
                if (p < 256) { sex[p] = s; sxid[p] = idx; }
            }
        }
    }
    __syncthreads();
    int m = s_n < 256 ? s_n : 256;

    for (int i = t; i < NCLASS; i += 256) out[b * NCLASS + i] = 0.f;
    __syncthreads();

    if (t == 0) {
        float vsel[TOPK]; int isel[TOPK];
        for (int k = 0; k < TOPK; k++) {
            float bv = NEGBIG; int bidx = 0x7fffffff; int bp = -1;
            for (int i = 0; i < m; i++) {
                float v = sex[i]; int id = sxid[i];
                if (v > bv || (v == bv && id < bidx)) { bv = v; bidx = id; bp = i; }
            }
            vsel[k] = bv; isel[k] = bidx;
            if (bp >= 0) sex[bp] = NEGBIG;
        }
        float v0 = vsel[0];
        for (int k = 0; k < TOPK; k++) {
            if (vsel[k] <= -1e29f) break;
            float w = expf((vsel[k] - v0) / 0.07f);
            out[b * NCLASS + labels[isel[k]]] += w;
        }
    }
}

// ---------------------------------------------------------------------------
extern "C" void kernel_launch(void* const* d_in, const int* in_sizes, int n_in,
                              void* d_out, int out_size)
{
    const float* x     = (const float*)d_in[0];
    const float* mean1 = (const float*)d_in[1];
    const float* std1  = (const float*)d_in[2];
    const float* P     = (const float*)d_in[3];
    const float* mean2 = (const float*)d_in[4];
    const float* std2  = (const float*)d_in[5];
    const float* train = (const float*)d_in[6];
    const int*   lbl   = (const int*)d_in[7];
    float* out = (float*)d_out;

    (void)in_sizes; (void)n_in; (void)out_size;

    const int smem_bytes = SM_TOTAL + 1024;   // + alignment slack
    cudaFuncSetAttribute(k_gemm_ws, cudaFuncAttributeMaxDynamicSharedMemorySize, smem_bytes);

    k_conv<<<NTILES, 256>>>(train);
    k_prep<<<B_ROWS / 2, 256>>>(x, mean1, std1, P, mean2, std2);
    k_gemm_ws<<<2 * NSTREAMS, 288, smem_bytes>>>(train);
    k_final<<<B_ROWS, 256>>>(train, lbl, out);
}